// round 17
// baseline (speedup 1.0000x reference)
#include <cuda_runtime.h>
#include <math.h>

#define NT 365
#define NTP 368          // 23 chunks of 16
#define NCHUNK 23
#define CH 16
#define BP 34            // buf row pitch in ull units (272 B, 16B-aligned)
#define FPITCH 369       // sForc row pitch (float4)
#define PPITCH 369       // sPart row pitch (floats)
#define NS 1024
#define NH 64
#define NG 32
#define NW 514
#define SPB 8            // sites per block (1 warp per site)
#define THREADS 256

typedef unsigned long long ull;

__device__ __forceinline__ float sigm(float x) { return 1.0f / (1.0f + expf(-x)); }

// ---- packed f32x2 helpers (sm_100+): pack movs are register-pairing hints ----
__device__ __forceinline__ float2 f2add(float2 a, float2 b) {
    float2 r;
    asm("{.reg .b64 ra, rb, rc;\n\t"
        "mov.b64 ra, {%2,%3};\n\t mov.b64 rb, {%4,%5};\n\t"
        "add.rn.f32x2 rc, ra, rb;\n\t mov.b64 {%0,%1}, rc;}"
        : "=f"(r.x), "=f"(r.y) : "f"(a.x), "f"(a.y), "f"(b.x), "f"(b.y));
    return r;
}
__device__ __forceinline__ float2 f2sub(float2 a, float2 b) {
    float2 r;
    asm("{.reg .b64 ra, rb, rc;\n\t"
        "mov.b64 ra, {%2,%3};\n\t mov.b64 rb, {%4,%5};\n\t"
        "sub.rn.f32x2 rc, ra, rb;\n\t mov.b64 {%0,%1}, rc;}"
        : "=f"(r.x), "=f"(r.y) : "f"(a.x), "f"(a.y), "f"(b.x), "f"(b.y));
    return r;
}
__device__ __forceinline__ float2 f2mul(float2 a, float2 b) {
    float2 r;
    asm("{.reg .b64 ra, rb, rc;\n\t"
        "mov.b64 ra, {%2,%3};\n\t mov.b64 rb, {%4,%5};\n\t"
        "mul.rn.f32x2 rc, ra, rb;\n\t mov.b64 {%0,%1}, rc;}"
        : "=f"(r.x), "=f"(r.y) : "f"(a.x), "f"(a.y), "f"(b.x), "f"(b.y));
    return r;
}
__device__ __forceinline__ float2 f2fma(float2 a, float2 b, float2 c) {
    float2 r;
    asm("{.reg .b64 ra, rb, rc, rd;\n\t"
        "mov.b64 ra, {%2,%3};\n\t mov.b64 rb, {%4,%5};\n\t mov.b64 rc, {%6,%7};\n\t"
        "fma.rn.f32x2 rd, ra, rb, rc;\n\t mov.b64 {%0,%1}, rd;}"
        : "=f"(r.x), "=f"(r.y)
        : "f"(a.x), "f"(a.y), "f"(b.x), "f"(b.y), "f"(c.x), "f"(c.y));
    return r;
}
__device__ __forceinline__ float2 f2min(float2 a, float2 b) {
    return make_float2(fminf(a.x, b.x), fminf(a.y, b.y));
}
__device__ __forceinline__ float2 f2max(float2 a, float2 b) {
    return make_float2(fmaxf(a.x, b.x), fmaxf(a.y, b.y));
}

// Dynamic smem layout (bytes):
#define OFF_BUF   (SPB * FPITCH * 16)              // 47232
#define OFF_PART  (OFF_BUF + SPB * CH * BP * 8)    // +34816 = 82048
#define OFF_XC    (OFF_PART + SPB * PPITCH * 4)    // +11808 = 93856
#define OFF_TAIL  (OFF_XC + SPB * NG * 4)          // +1024  = 94880
#define SMEM_TOTAL (OFF_TAIL + 64)

extern __shared__ __align__(16) char smemRaw[];

__global__ void __launch_bounds__(THREADS)
waternet_kernel(const float* __restrict__ x,
                const float* __restrict__ xc,
                const float* __restrict__ fc_w,
                const float* __restrict__ fc_b,
                float* __restrict__ out) {
    float4* sForc = reinterpret_cast<float4*>(smemRaw);                 // [SPB][FPITCH]
    float2* sBuf  = reinterpret_cast<float2*>(smemRaw + OFF_BUF);       // [SPB][CH*BP]
    float4* sFW4  = reinterpret_cast<float4*>(smemRaw + OFF_BUF);       // [64][9] overlay
    float*  sPart = reinterpret_cast<float*>(smemRaw + OFF_PART);       // [SPB][PPITCH]
    float*  sXc   = reinterpret_cast<float*>(smemRaw + OFF_XC);         // [SPB][NG]
    float*  sQb   = reinterpret_cast<float*>(smemRaw + OFF_TAIL);       // [8]

    const int tid  = threadIdx.x;
    const int warp = tid >> 5;          // 0..7 == site in block
    const int lane = tid & 31;
    const int si   = warp;
    const int s0   = blockIdx.x * SPB;
    const int s    = s0 + si;

    // ---- stage xc (coalesced) ----
    sXc[tid] = xc[s0 * NG + tid];

    // ---- forcing staging: coalesced (8 consecutive sites per t) ----
    const float4* x4 = reinterpret_cast<const float4*>(x);
    for (int idx = tid; idx < NTP * SPB; idx += THREADS) {
        const int t  = idx >> 3;
        const int sl = idx & 7;
        float4 o = make_float4(0.f, 0.f, 0.f, 0.f);
        if (t < NT) {
            float4 xi = x4[t * NS + s0 + sl];
            float P = xi.x, E = xi.y, T1 = xi.z, T2 = xi.w;
            float Ta = (T1 + T2) * 0.5f;
            bool valid  = (T1 < 0.0f) && (T2 > 0.0f);
            float denom = valid ? (T2 - T1) : 1.0f;
            float ratio = valid ? (T1 + T2) / denom : 0.0f;
            ratio = fminf(fmaxf(ratio, -0.999999f), 0.999999f);
            float rP = 1.0f - acosf(ratio) / 3.1415f;
            if (T1 >= 0.0f) rP = 1.0f;
            if (T2 <= 0.0f) rP = 0.0f;
            o.x = (1.0f - rP) * P;      // Ps
            o.y = rP * P;               // Pl
            o.z = fmaxf(Ta, 0.0f);      // ReLU(Ta)
            o.w = E;
        }
        sForc[sl * FPITCH + t] = o;
    }
    __syncthreads();

    // ---- GEMM: 8 chunks of 64 rows staged in smem; each thread dots 2 h ----
    const float4* fw4 = reinterpret_cast<const float4*>(fc_w);
    const float4* xs4 = reinterpret_cast<const float4*>(sXc + si * NG);
    float wv0[8], wv1[8];
    #pragma unroll
    for (int c = 0; c < 8; ++c) {
        #pragma unroll
        for (int i = 0; i < 2; ++i) {
            const int idx = tid + (i << 8);
            const int jl  = idx >> 3;
            const int qq  = idx & 7;
            sFW4[jl * 9 + qq] = fw4[(c * 64 + jl) * 8 + qq];
        }
        __syncthreads();
        float a0 = 0.0f, a1 = 0.0f;
        #pragma unroll
        for (int q = 0; q < 8; ++q) {
            const float4 xv = xs4[q];              // warp-broadcast LDS
            const float4 v0 = sFW4[lane * 9 + q];
            const float4 v1 = sFW4[(lane + 32) * 9 + q];
            a0 += v0.x * xv.x + v0.y * xv.y + v0.z * xv.z + v0.w * xv.w;
            a1 += v1.x * xv.x + v1.y * xv.y + v1.z * xv.z + v1.w * xv.w;
        }
        wv0[c] = a0;
        wv1[c] = a1;
        __syncthreads();
    }
    #pragma unroll
    for (int c = 0; c < 8; ++c) {
        wv0[c] += fc_b[c * NH + lane];
        wv1[c] += fc_b[c * NH + lane + 32];
    }

    // ---- qb: warp 0 lanes 0..7, one site each ----
    if (warp == 0 && lane < SPB) {
        float acc = 0.0f;
        const float* xr = sXc + lane * NG;
        #pragma unroll
        for (int q = 0; q < 8; ++q) {
            float4 v = fw4[513 * 8 + q];
            acc += v.x * xr[q * 4 + 0] + v.y * xr[q * 4 + 1]
                 + v.z * xr[q * 4 + 2] + v.w * xr[q * 4 + 3];
        }
        sQb[lane] = fmaxf(acc + fc_b[513], 0.0f) * (1.0f / 64.0f);
    }

    // ---- activations (both h halves) ----
    float gm0   = expf(wv0[0]) + 1.0f,  gm1   = expf(wv1[0]) + 1.0f;
    float nge0  = -2.0f * sigm(wv0[1]), nge1  = -2.0f * sigm(wv1[1]);
    float go0   = sigm(wv0[2]),         go1   = sigm(wv1[2]);
    float gl0   = expf(2.0f * wv0[3]),  gl1   = expf(2.0f * wv1[3]);
    float a0r   = wv0[4],               a1r   = wv1[4];
    float gb0   = sigm(wv0[5]),         gb1   = sigm(wv1[5]);
    float kb0   = sigm(wv0[6]) * 0.1f,  kb1s  = sigm(wv1[6]) * 0.1f;
    float gi0   = sigm(wv0[7]),         gi1   = sigm(wv1[7]);

    // ---- softmax over the site's 64 h: intra-warp (2 per lane) ----
    float m = fmaxf(a0r, a1r);
    #pragma unroll
    for (int o = 16; o; o >>= 1) m = fmaxf(m, __shfl_xor_sync(0xffffffffu, m, o));
    float e0 = expf(a0r - m), e1 = expf(a1r - m);
    float ssum = e0 + e1;
    #pragma unroll
    for (int o = 16; o; o >>= 1) ssum += __shfl_xor_sync(0xffffffffu, ssum, o);
    const float inv = 1.0f / ssum;
    const float ga0 = e0 * inv, ga1 = e1 * inv;

    // ---- per-lane packed constants ----
    const float2 gm2   = make_float2(gm0, gm1);
    const float2 nge2  = make_float2(nge0, nge1);
    const float2 gi2   = make_float2(gi0, gi1);
    const float2 gl2   = make_float2(gl0, gl1);
    const float2 ngo2  = make_float2(-go0, -go1);
    const float2 gogb2 = make_float2(go0 * gb0, go1 * gb1);
    const float2 kb12  = make_float2(1.0f - kb0, 1.0f - kb1s);
    const float2 ga2   = make_float2(ga0, ga1);
    const float2 chc2  = make_float2(go0 * (1.0f - gb0) * ga0 - ga0,
                                     go1 * (1.0f - gb1) * ga1 - ga1);
    const float2 cg2   = make_float2(kb0 * ga0, kb1s * ga1);
    const float2 zero2 = make_float2(0.0f, 0.0f);

    // ---- sequential scan: packed f32x2, per-warp, no block barriers ----
    float2* buf = sBuf + warp * (CH * BP);
    const float4* forc = sForc + si * FPITCH;
    float* part = sPart + warp * PPITCH;
    const int rt = lane & 15;            // 2 lanes per t (partner = lane^16)
    const int rq = lane >> 4;

    float2 S0 = zero2, H0 = zero2, G0 = zero2;

    for (int c = 0; c < NCHUNK; ++c) {
        const float4* fp = forc + c * CH;
        #pragma unroll
        for (int tt = 0; tt < CH; ++tt) {
            const float4 f = fp[tt];             // broadcast LDS.128
            const float2 bx = make_float2(f.x, f.x);
            const float2 by = make_float2(f.y, f.y);
            const float2 bz = make_float2(f.z, f.z);
            const float2 bw = make_float2(f.w, f.w);
            float2 mt  = f2mul(bz, gm2);
            float2 Sm  = f2min(S0, mt);
            float2 At  = f2fma(bw, nge2, f2mul(by, gi2));   // Pl*gi - E*ge
            float2 H   = f2max(f2add(f2add(H0, Sm), At), zero2);
            float2 Hc  = f2min(H, gl2);
            float2 t1  = f2fma(ngo2, Hc, H);                // H - go*Hc
            float2 g2v = f2fma(Hc, gogb2, G0);
            H0 = f2min(t1, gl2);
            G0 = f2mul(g2v, kb12);
            S0 = f2add(f2sub(S0, Sm), bx);
            float2 y2  = f2mul(g2v, cg2);
            y2 = f2fma(Hc, chc2, y2);
            y2 = f2fma(H, ga2, y2);
            buf[tt * BP + lane] = y2;            // STS.64, conflict-free
        }
        __syncwarp();
        // reduce: lane (rt, rq) sums 32 contiguous floats (8x float4)
        const float* fb = reinterpret_cast<const float*>(buf) + rt * (BP * 2) + rq * 32;
        float p = 0.0f;
        #pragma unroll
        for (int k = 0; k < 8; ++k) {
            const float4 v = *reinterpret_cast<const float4*>(fb + 4 * k);
            p += (v.x + v.y) + (v.z + v.w);
        }
        p += __shfl_xor_sync(0xffffffffu, p, 16);
        if (rq == 0) part[c * CH + rt] = p;
        __syncwarp();
    }

    // ---- epilogue: add qb, near-coalesced stores ----
    __syncthreads();
    {
        const int sl = tid & 7;
        const float qb = sQb[sl];
        for (int t = tid >> 3; t < NT; t += 32) {
            out[t * NS + s0 + sl] = sPart[sl * PPITCH + t] + qb;
        }
    }
}

// ---------------------------------------------------------------------------
extern "C" void kernel_launch(void* const* d_in, const int* in_sizes, int n_in,
                              void* d_out, int out_size) {
    const float* x    = (const float*)d_in[0];   // [NT, NS, 4]
    const float* xc   = (const float*)d_in[1];   // [NS, NG]
    const float* fc_w = (const float*)d_in[2];   // [NW, NG]
    const float* fc_b = (const float*)d_in[3];   // [NW]
    float* out = (float*)d_out;                  // [NT, NS]

    static int configured = 0;
    if (!configured) {
        cudaFuncSetAttribute(waternet_kernel,
                             cudaFuncAttributeMaxDynamicSharedMemorySize,
                             SMEM_TOTAL);
        configured = 1;
    }
    waternet_kernel<<<NS / SPB, THREADS, SMEM_TOTAL>>>(x, xc, fc_w, fc_b, out);
}